// round 4
// baseline (speedup 1.0000x reference)
#include <cuda_runtime.h>

// AdEx neuron scan, T=2048, N=32768. spikes[t,n] in f32 {0,1}.
// w == 0 identically (A=0, B=0, w0=0) -> dropped.
// Fast path (valid while V <= -20 mV, where 2*exp((V-0.6)/2) < 7e-5 cannot
// affect spiking):  V' = 0.995*V + 0.005*(I - 70), spike = 0.
// Rare path: exact per-batch redo (exp + spike/reset), stores spike values.
//
// R4 change vs R3: split into TWO kernels (stream-ordered, graph-capturable):
//   1) zero_kernel: pure float4 memset of the whole output (write-only phase,
//      no read/write turnaround, 1184 = 8*148 blocks -> perfect wave balance).
//   2) scan_kernel: load+FFMA only; NO stores and NO barriers on the fast
//      path. 1024 one-warp blocks (98.8% wave balance), unroll-32
//      double-buffered loads for continuous MLP. Rare fallback overwrites
//      zeros (ordered behind zero_kernel by the stream).

#define AX_N 32768
#define U 32

// ---------------------------------------------------------------- zero fill
__global__ void __launch_bounds__(256)
zero_kernel(float4* __restrict__ S4, int n4) {
    const float4 z = make_float4(0.f, 0.f, 0.f, 0.f);
    int i = blockIdx.x * blockDim.x + threadIdx.x;
    const int stride = gridDim.x * blockDim.x;
    for (; i < n4; i += stride)
        __stcs(S4 + i, z);
}

// ---------------------------------------------------------------- scan
__device__ __forceinline__ void load_batch(const float* __restrict__ ip,
                                           int tbase, float (&buf)[U]) {
    #pragma unroll
    for (int k = 0; k < U; ++k)
        buf[k] = __ldcs(ip + (size_t)(tbase + k) * AX_N);
}

__device__ __forceinline__ void compute_batch(float* __restrict__ op, int tbase,
                                              const float (&buf)[U], float& V) {
    const float Vs = V;
    float v = V;
    float m = V;
    #pragma unroll
    for (int k = 0; k < U; ++k) {
        v = fmaf(0.995f, v, fmaf(0.005f, buf[k], -0.35f));
        m = fmaxf(m, v);
    }
    if (__any_sync(0xFFFFFFFFu, m > -20.0f)) {
        // Exact AdEx redo for this batch (rare; correctness fallback).
        v = Vs;
        #pragma unroll 1
        for (int k = 0; k < U; ++k) {
            const float e = 2.0f * expf((v - 0.6f) * 0.5f);
            float Vn = v + 0.005f * ((-70.0f - v) + e + buf[k]);
            float s = 0.0f;
            if (Vn >= 30.0f) { s = 1.0f; Vn = -65.0f; }
            v = Vn;
            __stcs(op + (size_t)(tbase + k) * AX_N, s);
        }
    }
    V = v;
}

__global__ void __launch_bounds__(32, 1)
scan_kernel(const float* __restrict__ I, float* __restrict__ S, int T) {
    const int n = blockIdx.x * 32 + threadIdx.x;   // 1024 blocks x 1 warp
    if (n >= AX_N) return;

    const float* ip = I + n;
    float* op = S + n;

    float V = -70.0f;   // E_L
    float bufA[U], bufB[U];

    const int nb = T / U;          // 64 for T=2048
    int t = 0;

    if (nb > 0) {
        load_batch(ip, 0, bufA);
        int b = 0;
        for (; b + 2 <= nb; b += 2) {
            load_batch(ip, (b + 1) * U, bufB);       // prefetch next batch
            compute_batch(op, b * U, bufA, V);
            if (b + 2 < nb) load_batch(ip, (b + 2) * U, bufA);
            compute_batch(op, (b + 1) * U, bufB, V);
        }
        if (b < nb) {                                // odd nb
            compute_batch(op, b * U, bufA, V);
            b++;
        }
        t = nb * U;
    }

    // Scalar tail (T % U != 0): always-exact path with direct stores.
    for (; t < T; ++t) {
        const float iv = __ldcs(ip + (size_t)t * AX_N);
        const float e = 2.0f * expf((V - 0.6f) * 0.5f);
        float Vn = V + 0.005f * ((-70.0f - V) + e + iv);
        float s = 0.0f;
        if (Vn >= 30.0f) { s = 1.0f; Vn = -65.0f; }
        V = Vn;
        __stcs(op + (size_t)t * AX_N, s);
    }
}

extern "C" void kernel_launch(void* const* d_in, const int* in_sizes, int n_in,
                              void* d_out, int out_size) {
    const float* I = (const float*)d_in[0];
    float* S = (float*)d_out;
    const int T = in_sizes[0] / AX_N;   // 2048

    // Phase 1: zero the whole output (write-only stream, perfect balance).
    const int n4 = out_size / 4;        // out_size divisible by 4 here
    zero_kernel<<<1184, 256>>>((float4*)S, n4);

    // Phase 2: scan (read-only stream on the fast path).
    scan_kernel<<<AX_N / 32, 32>>>(I, S, T);
}